// round 1
// baseline (speedup 1.0000x reference)
#include <cuda_runtime.h>
#include <cuda_bf16.h>
#include <cstdint>

// Problem constants
#define CCN   256
#define STD   12
#define FS    64
#define HALF  32
#define NIMG  (CCN*STD)          // 3072
#define DIM   2048               // FS*HALF
#define IMGE  (FS*FS)            // 4096

static const size_t T_FULL  = (size_t)NIMG * IMGE;        // 12,582,912 elems per full tensor
static const size_t T_SLICE = (size_t)CCN * 11 * IMGE;    // 11,534,336 elems per [:,1:] slice

// Output section offsets (floats)
static const size_t S0 = 0;                    // x
static const size_t S1 = S0 + T_FULL;          // phiX
static const size_t S2 = S1 + T_FULL;          // dephiPhiX
static const size_t S3 = S2 + T_FULL;          // kPhix
static const size_t S4 = S3 + T_FULL;          // dePhiKPhiX
static const size_t S5 = S4 + T_FULL;          // x[:,1:]
static const size_t S6 = S5 + T_SLICE;         // phiX[:,1:]

// Scratch (device globals — no runtime allocation allowed)
__device__ float g_A[(size_t)NIMG * DIM];
__device__ float g_B[(size_t)NIMG * DIM];
__device__ float g_aF[DIM], g_cF[DIM], g_aG[DIM], g_cG[DIM];

// ---------------------------------------------------------------------------
// BN coefficient precompute: a = g*rsqrt(v+eps); c = be - a*m
// ---------------------------------------------------------------------------
__global__ void bncoef_kernel(const float* __restrict__ g1, const float* __restrict__ be1,
                              const float* __restrict__ m1, const float* __restrict__ v1,
                              const float* __restrict__ g3, const float* __restrict__ be3,
                              const float* __restrict__ m3, const float* __restrict__ v3)
{
    int k = blockIdx.x * blockDim.x + threadIdx.x;
    if (k < DIM) {
        float aF = g1[k] * rsqrtf(v1[k] + 1e-3f);
        g_aF[k] = aF;  g_cF[k] = be1[k] - aF * m1[k];
        float aG = g3[k] * rsqrtf(v3[k] + 1e-3f);
        g_aG[k] = aG;  g_cG[k] = be3[k] - aG * m3[k];
    }
}

// ---------------------------------------------------------------------------
// Checkerboard split: u1[n,i,j] = x[n,i,2j+(i%2)], u2[n,i,j] = x[n,i,2j+1-(i%2)]
// ---------------------------------------------------------------------------
__global__ void split_kernel(const float* __restrict__ x, float* __restrict__ u1,
                             float* __restrict__ u2)
{
    size_t idx = (size_t)blockIdx.x * blockDim.x + threadIdx.x;
    if (idx >= (size_t)NIMG * DIM) return;
    int n = (int)(idx >> 11);
    int i = (int)((idx >> 5) & 63);
    int j = (int)(idx & 31);
    int p = i & 1;
    const float* row = x + ((size_t)n << 12) + ((size_t)i << 6) + ((size_t)j << 1);
    u1[idx] = row[p];
    u2[idx] = row[1 - p];
}

// ---------------------------------------------------------------------------
// Mix: y[n,i,c] built from v1 (even-col role) and w2 (odd-col role)
//   even row i: c even -> v1[c/2];           c odd  -> w2[(c-1)/2]
//   odd  row i: c odd  -> v1[((c+1)/2)%32];  c even -> w2[(c/2+31)%32]
// ---------------------------------------------------------------------------
__global__ void mix_kernel(const float* __restrict__ v1b, const float* __restrict__ w2b,
                           float* __restrict__ y)
{
    size_t idx = (size_t)blockIdx.x * blockDim.x + threadIdx.x;
    if (idx >= (size_t)NIMG * IMGE) return;
    int n = (int)(idx >> 12);
    int r = (int)((idx >> 6) & 63);
    int c = (int)(idx & 63);
    const float* v1 = v1b + ((size_t)n << 11) + ((size_t)r << 5);
    const float* w2 = w2b + ((size_t)n << 11) + ((size_t)r << 5);
    float val;
    if ((r & 1) == 0) {
        val = (c & 1) ? w2[(c - 1) >> 1] : v1[c >> 1];
    } else {
        val = (c & 1) ? v1[((c + 1) >> 1) & 31] : w2[((c >> 1) + 31) & 31];
    }
    y[idx] = val;
}

// ---------------------------------------------------------------------------
// Fused BN + GEMM + epilogue:
//   out[n,j] = base[n,j] + sign * ( sum_k (a[k]*A[n,k]+c[k]) * W[k,j] + bias[j] )
// M=3072, K=2048, N=2048. base may alias out (in-place residual).
// 128x128 block tile, BK=8, 8x8 per thread, 256 threads.
// ---------------------------------------------------------------------------
#define BM 128
#define BN 128
#define BK 8
#define TM 8
#define TN 8

__global__ __launch_bounds__(256, 1)
void gemm_bn_kernel(const float* __restrict__ A, const float* __restrict__ W,
                    const float* __restrict__ bias,
                    const float* __restrict__ aC, const float* __restrict__ cC,
                    const float* base, float* out, float sign)
{
    const int K = DIM, N = DIM;
    __shared__ float As[BK][BM];
    __shared__ float Bs[BK][BN];

    int brow = blockIdx.y;   // M tile index
    int bcol = blockIdx.x;   // N tile index
    int tid  = threadIdx.x;
    int tcol = tid & 15;     // 0..15
    int trow = tid >> 4;     // 0..15

    float acc[TM][TN];
    #pragma unroll
    for (int i = 0; i < TM; i++)
        #pragma unroll
        for (int j = 0; j < TN; j++) acc[i][j] = 0.f;
    float regA[TM], regB[TN];

    // A tile load mapping: 128 rows x 8 k -> thread loads one float4 along K
    int aRow  = tid >> 1;          // 0..127
    int aColV = (tid & 1) << 2;    // 0 or 4
    // B tile load: 8 k-rows x 128 n -> one float4 along N
    int bRow  = tid >> 5;          // 0..7
    int bColV = (tid & 31) << 2;   // 0..124

    const float* Aptr = A + (size_t)(brow * BM) * K;
    const float* Wptr = W + bcol * BN;

    for (int k0 = 0; k0 < K; k0 += BK) {
        float4 av = *reinterpret_cast<const float4*>(Aptr + (size_t)aRow * K + k0 + aColV);
        float4 aa = *reinterpret_cast<const float4*>(aC + k0 + aColV);
        float4 cc = *reinterpret_cast<const float4*>(cC + k0 + aColV);
        As[aColV + 0][aRow] = av.x * aa.x + cc.x;
        As[aColV + 1][aRow] = av.y * aa.y + cc.y;
        As[aColV + 2][aRow] = av.z * aa.z + cc.z;
        As[aColV + 3][aRow] = av.w * aa.w + cc.w;
        float4 bv = *reinterpret_cast<const float4*>(Wptr + (size_t)(k0 + bRow) * N + bColV);
        *reinterpret_cast<float4*>(&Bs[bRow][bColV]) = bv;
        __syncthreads();

        #pragma unroll
        for (int kk = 0; kk < BK; kk++) {
            #pragma unroll
            for (int i = 0; i < TM; i++) regA[i] = As[kk][trow * TM + i];
            #pragma unroll
            for (int j = 0; j < TN; j++) regB[j] = Bs[kk][tcol * TN + j];
            #pragma unroll
            for (int i = 0; i < TM; i++)
                #pragma unroll
                for (int j = 0; j < TN; j++)
                    acc[i][j] += regA[i] * regB[j];
        }
        __syncthreads();
    }

    #pragma unroll
    for (int i = 0; i < TM; i++) {
        size_t gr = (size_t)(brow * BM + trow * TM + i);
        #pragma unroll
        for (int j0 = 0; j0 < TN; j0 += 4) {
            int gc = bcol * BN + tcol * TN + j0;
            float4 bs = *reinterpret_cast<const float4*>(bias + gc);
            float4 bb = *reinterpret_cast<const float4*>(base + gr * N + gc);
            float4 o;
            o.x = bb.x + sign * (acc[i][j0 + 0] + bs.x);
            o.y = bb.y + sign * (acc[i][j0 + 1] + bs.y);
            o.z = bb.z + sign * (acc[i][j0 + 2] + bs.z);
            o.w = bb.w + sign * (acc[i][j0 + 3] + bs.w);
            *reinterpret_cast<float4*>(out + gr * N + gc) = o;
        }
    }
}

// ---------------------------------------------------------------------------
// Koopman step: out image m=(n',s) with n'=q*4+b is phi image (b*64+q, s) @ kop
// ---------------------------------------------------------------------------
__global__ void koop_kernel(const float* __restrict__ phi, const float* __restrict__ kop,
                            float* __restrict__ outk)
{
    __shared__ float sk[64][64];
    __shared__ float si[64][64];
    int m = blockIdx.x;                 // output image 0..3071
    int nprime = m / STD, s = m % STD;
    int q = nprime >> 2, b = nprime & 3;
    int nin = b * 64 + q;
    const float* src = phi + (size_t)(nin * STD + s) * IMGE;
    float* dst = outk + (size_t)m * IMGE;
    int t = threadIdx.x;
    for (int e = t; e < IMGE; e += 256) {
        sk[e >> 6][e & 63] = kop[e];
        si[e >> 6][e & 63] = src[e];
    }
    __syncthreads();
    for (int e = t; e < IMGE; e += 256) {
        int i = e >> 6, c = e & 63;
        float acc = 0.f;
        #pragma unroll
        for (int j = 0; j < 64; j++) acc += si[i][j] * sk[j][c];
        dst[e] = acc;
    }
}

// ---------------------------------------------------------------------------
// [:,1:] slice copy: dst[n, s-1, :, :] = src[n, s, :, :] for s in 1..11
// ---------------------------------------------------------------------------
__global__ void slice_kernel(const float* __restrict__ src, float* __restrict__ dst)
{
    size_t idx = (size_t)blockIdx.x * blockDim.x + threadIdx.x;
    if (idx >= T_SLICE) return;
    size_t n = idx / ((size_t)11 * IMGE);
    size_t r = idx % ((size_t)11 * IMGE);
    size_t s = r / IMGE + 1;
    size_t e = r % IMGE;
    dst[idx] = src[(n * STD + s) * IMGE + e];
}

// ---------------------------------------------------------------------------
extern "C" void kernel_launch(void* const* d_in, const int* in_sizes, int n_in,
                              void* d_out, int out_size)
{
    const float* x   = (const float*)d_in[0];
    // d_in[1] = indexs (unused)
    const float* W1  = (const float*)d_in[2];
    const float* b1  = (const float*)d_in[3];
    const float* g1  = (const float*)d_in[4];
    const float* be1 = (const float*)d_in[5];
    const float* m1  = (const float*)d_in[6];
    const float* v1  = (const float*)d_in[7];
    const float* W3  = (const float*)d_in[8];
    const float* b3  = (const float*)d_in[9];
    const float* g3  = (const float*)d_in[10];
    const float* be3 = (const float*)d_in[11];
    const float* m3  = (const float*)d_in[12];
    const float* v3  = (const float*)d_in[13];
    const float* kop = (const float*)d_in[14];
    float* out = (float*)d_out;

    float* A;  cudaGetSymbolAddress((void**)&A,  g_A);
    float* B;  cudaGetSymbolAddress((void**)&B,  g_B);
    float* aF; cudaGetSymbolAddress((void**)&aF, g_aF);
    float* cF; cudaGetSymbolAddress((void**)&cF, g_cF);
    float* aG; cudaGetSymbolAddress((void**)&aG, g_aG);
    float* cG; cudaGetSymbolAddress((void**)&cG, g_cG);

    dim3 ggrid(DIM / BN, NIMG / BM);   // (16, 24)
    const int SPLIT_BLKS = (int)(((size_t)NIMG * DIM + 255) / 256);
    const int MIX_BLKS   = (int)(((size_t)NIMG * IMGE + 255) / 256);
    const int SLICE_BLKS = (int)((T_SLICE + 255) / 256);

    // BN coefficients
    bncoef_kernel<<<8, 256>>>(g1, be1, m1, v1, g3, be3, m3, v3);

    // Section 0: x  (plain copy)   Section 5: x[:,1:]
    cudaMemcpyAsync(out + S0, x, T_FULL * sizeof(float), cudaMemcpyDeviceToDevice);
    slice_kernel<<<SLICE_BLKS, 256>>>(x, out + S5);

    // ---- Encoder ----
    split_kernel<<<SPLIT_BLKS, 256>>>(x, A, B);                       // A=u1, B=u2
    gemm_bn_kernel<<<ggrid, 256>>>(B, W1, b1, aF, cF, A, A, +1.0f);   // A = v1 = u1 + F(u2)
    gemm_bn_kernel<<<ggrid, 256>>>(A, W3, b3, aG, cG, B, B, +1.0f);   // B = w2 = u2 + G(v1)
    mix_kernel<<<MIX_BLKS, 256>>>(A, B, out + S1);                    // phiX
    slice_kernel<<<SLICE_BLKS, 256>>>(out + S1, out + S6);            // phiX[:,1:]

    // ---- Decoder(phiX) ----
    split_kernel<<<SPLIT_BLKS, 256>>>(out + S1, A, B);                // A=w1, B=w2
    gemm_bn_kernel<<<ggrid, 256>>>(A, W3, b3, aG, cG, B, B, -1.0f);   // B = v2 = w2 - G(w1)
    gemm_bn_kernel<<<ggrid, 256>>>(B, W1, b1, aF, cF, A, A, -1.0f);   // A = u1 = w1 - F(v2)
    mix_kernel<<<MIX_BLKS, 256>>>(A, B, out + S2);                    // dephiPhiX

    // ---- Koopman ----
    koop_kernel<<<NIMG, 256>>>(out + S1, kop, out + S3);              // kPhix

    // ---- Decoder(kPhix) ----
    split_kernel<<<SPLIT_BLKS, 256>>>(out + S3, A, B);
    gemm_bn_kernel<<<ggrid, 256>>>(A, W3, b3, aG, cG, B, B, -1.0f);
    gemm_bn_kernel<<<ggrid, 256>>>(B, W1, b1, aF, cF, A, A, -1.0f);
    mix_kernel<<<MIX_BLKS, 256>>>(A, B, out + S4);                    // dePhiKPhiX
}

// round 3
// speedup vs baseline: 1.5154x; 1.5154x over previous
#include <cuda_runtime.h>
#include <cuda_bf16.h>
#include <cstdint>

// ---------------------------------------------------------------------------
// Problem constants
// ---------------------------------------------------------------------------
#define CCN   256
#define STD   12
#define FS    64
#define HALF  32
#define NIMG  (CCN*STD)          // 3072
#define DIM   2048               // FS*HALF
#define IMGE  (FS*FS)            // 4096

static const size_t T_FULL  = (size_t)NIMG * IMGE;
static const size_t T_SLICE = (size_t)CCN * 11 * IMGE;

// Output section offsets (floats)
static const size_t S0 = 0;                    // x
static const size_t S1 = S0 + T_FULL;          // phiX
static const size_t S2 = S1 + T_FULL;          // dephiPhiX
static const size_t S3 = S2 + T_FULL;          // kPhix
static const size_t S4 = S3 + T_FULL;          // dePhiKPhiX
static const size_t S5 = S4 + T_FULL;          // x[:,1:]
static const size_t S6 = S5 + T_SLICE;         // phiX[:,1:]

// ---------------------------------------------------------------------------
// Scratch (device globals — no runtime allocation allowed)
// ---------------------------------------------------------------------------
__device__ float g_A [(size_t)NIMG * DIM];
__device__ float g_B [(size_t)NIMG * DIM];
__device__ float g_H0[(size_t)NIMG * DIM];
__device__ float g_L0[(size_t)NIMG * DIM];
__device__ float g_H1[(size_t)NIMG * DIM];
__device__ float g_L1[(size_t)NIMG * DIM];
__device__ float g_W1Thi[(size_t)DIM * DIM];   // W1^T hi  [N,K]
__device__ float g_W1Tlo[(size_t)DIM * DIM];
__device__ float g_W3Thi[(size_t)DIM * DIM];
__device__ float g_W3Tlo[(size_t)DIM * DIM];
__device__ float g_aF[DIM], g_cF[DIM], g_aG[DIM], g_cG[DIM];

// ---------------------------------------------------------------------------
// Helpers (base sm_103 target only — NO tcgen05 / arch-'a' features)
// ---------------------------------------------------------------------------
__device__ __forceinline__ float tf32r(float x) {
    uint32_t u;
    asm("cvt.rna.tf32.f32 %0, %1;" : "=r"(u) : "f"(x));
    return __uint_as_float(u);
}

__device__ __forceinline__ uint32_t smem_u32(const void* p) {
    uint32_t a;
    asm("{ .reg .u64 t; cvta.to.shared.u64 t, %1; cvt.u32.u64 %0, t; }" : "=r"(a) : "l"(p));
    return a;
}

__device__ __forceinline__ void cp16(uint32_t saddr, const void* gptr) {
    asm volatile("cp.async.cg.shared.global [%0], [%1], 16;" :: "r"(saddr), "l"(gptr));
}
#define CP_COMMIT() asm volatile("cp.async.commit_group;" ::: "memory")
#define CP_WAIT(n)  asm volatile("cp.async.wait_group %0;" :: "n"(n) : "memory")

__device__ __forceinline__ void mma_tf32(float* d, const uint32_t* a, const uint32_t* b) {
    asm volatile(
        "mma.sync.aligned.m16n8k8.row.col.f32.tf32.tf32.f32 "
        "{%0,%1,%2,%3}, {%4,%5,%6,%7}, {%8,%9}, {%0,%1,%2,%3};"
        : "+f"(d[0]), "+f"(d[1]), "+f"(d[2]), "+f"(d[3])
        : "r"(a[0]), "r"(a[1]), "r"(a[2]), "r"(a[3]), "r"(b[0]), "r"(b[1]));
}

// ---------------------------------------------------------------------------
// BN coefficient precompute
// ---------------------------------------------------------------------------
__global__ void bncoef_kernel(const float* __restrict__ g1, const float* __restrict__ be1,
                              const float* __restrict__ m1, const float* __restrict__ v1,
                              const float* __restrict__ g3, const float* __restrict__ be3,
                              const float* __restrict__ m3, const float* __restrict__ v3)
{
    int k = blockIdx.x * blockDim.x + threadIdx.x;
    if (k < DIM) {
        float aF = g1[k] * rsqrtf(v1[k] + 1e-3f);
        g_aF[k] = aF;  g_cF[k] = be1[k] - aF * m1[k];
        float aG = g3[k] * rsqrtf(v3[k] + 1e-3f);
        g_aG[k] = aG;  g_cG[k] = be3[k] - aG * m3[k];
    }
}

// ---------------------------------------------------------------------------
// Weight prep: W [K,N] -> W^T [N,K] split into tf32 hi/lo planes
// ---------------------------------------------------------------------------
__global__ void wprep_kernel(const float* __restrict__ W, float* __restrict__ Thi,
                             float* __restrict__ Tlo)
{
    __shared__ float t[32][33];
    int bn = blockIdx.x * 32;
    int bk = blockIdx.y * 32;
    int tx = threadIdx.x, ty = threadIdx.y;   // 32 x 8
    #pragma unroll
    for (int i = 0; i < 32; i += 8)
        t[ty + i][tx] = W[(size_t)(bk + ty + i) * DIM + bn + tx];
    __syncthreads();
    #pragma unroll
    for (int i = 0; i < 32; i += 8) {
        float v = t[tx][ty + i];
        float h = tf32r(v);
        size_t o = (size_t)(bn + ty + i) * DIM + bk + tx;
        Thi[o] = h;
        Tlo[o] = tf32r(v - h);
    }
}

// ---------------------------------------------------------------------------
// Checkerboard split + BN + tf32 hi/lo prep of one half
// ---------------------------------------------------------------------------
__global__ void split_prep_kernel(const float* __restrict__ x, float* __restrict__ u1,
                                  float* __restrict__ u2,
                                  const float* __restrict__ aC, const float* __restrict__ cC,
                                  float* __restrict__ hi, float* __restrict__ lo,
                                  int prep_first)
{
    size_t idx = (size_t)blockIdx.x * blockDim.x + threadIdx.x;
    if (idx >= (size_t)NIMG * DIM) return;
    int n = (int)(idx >> 11);
    int i = (int)((idx >> 5) & 63);
    int j = (int)(idx & 31);
    int p = i & 1;
    const float* row = x + ((size_t)n << 12) + ((size_t)i << 6) + ((size_t)j << 1);
    float v1 = row[p];
    float v2 = row[1 - p];
    u1[idx] = v1;
    u2[idx] = v2;
    int k = (int)(idx & 2047);
    float s = aC[k] * (prep_first ? v1 : v2) + cC[k];
    float h = tf32r(s);
    hi[idx] = h;
    lo[idx] = tf32r(s - h);
}

// ---------------------------------------------------------------------------
// Mix
// ---------------------------------------------------------------------------
__global__ void mix_kernel(const float* __restrict__ v1b, const float* __restrict__ w2b,
                           float* __restrict__ y)
{
    size_t idx = (size_t)blockIdx.x * blockDim.x + threadIdx.x;
    if (idx >= (size_t)NIMG * IMGE) return;
    int n = (int)(idx >> 12);
    int r = (int)((idx >> 6) & 63);
    int c = (int)(idx & 63);
    const float* v1 = v1b + ((size_t)n << 11) + ((size_t)r << 5);
    const float* w2 = w2b + ((size_t)n << 11) + ((size_t)r << 5);
    float val;
    if ((r & 1) == 0) {
        val = (c & 1) ? w2[(c - 1) >> 1] : v1[c >> 1];
    } else {
        val = (c & 1) ? v1[((c + 1) >> 1) & 31] : w2[((c >> 1) + 31) & 31];
    }
    y[idx] = val;
}

// ---------------------------------------------------------------------------
// Koopman step
// ---------------------------------------------------------------------------
__global__ void koop_kernel(const float* __restrict__ phi, const float* __restrict__ kop,
                            float* __restrict__ outk)
{
    __shared__ float sk[64][64];
    __shared__ float si[64][64];
    int m = blockIdx.x;
    int nprime = m / STD, s = m % STD;
    int q = nprime >> 2, b = nprime & 3;
    int nin = b * 64 + q;
    const float* src = phi + (size_t)(nin * STD + s) * IMGE;
    float* dst = outk + (size_t)m * IMGE;
    int t = threadIdx.x;
    for (int e = t; e < IMGE; e += 256) {
        sk[e >> 6][e & 63] = kop[e];
        si[e >> 6][e & 63] = src[e];
    }
    __syncthreads();
    for (int e = t; e < IMGE; e += 256) {
        int i = e >> 6, c = e & 63;
        float acc = 0.f;
        #pragma unroll
        for (int j = 0; j < 64; j++) acc += si[i][j] * sk[j][c];
        dst[e] = acc;
    }
}

// ---------------------------------------------------------------------------
// [:,1:] slice copy
// ---------------------------------------------------------------------------
__global__ void slice_kernel(const float* __restrict__ src, float* __restrict__ dst)
{
    size_t idx = (size_t)blockIdx.x * blockDim.x + threadIdx.x;
    if (idx >= T_SLICE) return;
    size_t n = idx / ((size_t)11 * IMGE);
    size_t r = idx % ((size_t)11 * IMGE);
    size_t s = r / IMGE + 1;
    size_t e = r % IMGE;
    dst[idx] = src[(n * STD + s) * IMGE + e];
}

// ---------------------------------------------------------------------------
// TF32 mma.sync GEMM with 3-term hi/lo emulation.
//   out[m,n] = base[m,n] + sign*( sum_k A[m,k]*WT[n,k] + bias[n] )
// A planes [M,K] row-major; WT planes [N,K] row-major.
// CTA tile 128x128, BK=16, 8 warps (2x4), warp tile 64x32, 3-stage cp.async.
// ---------------------------------------------------------------------------
#define GM 128
#define GN 128
#define GK 16
#define NT_K (DIM / GK)          // 128
#define PITCH 20                 // floats per smem row (16 + 4 pad) -> conflict-free
#define PLANE_F (128 * PITCH)    // 2560 floats per plane
#define STAGE_F (4 * PLANE_F)    // 10240 floats per stage
#define STAGES 3
#define SM_TOTAL (STAGES * STAGE_F * 4)   // 122880 bytes

__global__ void __launch_bounds__(256, 1)
gemm_tc_kernel(const float* __restrict__ Ahi, const float* __restrict__ Alo,
               const float* __restrict__ Whi, const float* __restrict__ Wlo,
               const float* __restrict__ bias, const float* base, float* outp, float sign,
               const float* __restrict__ aN, const float* __restrict__ cN,
               float* eHi, float* eLo, int emit)
{
    extern __shared__ float smem[];
    const int tid  = threadIdx.x;
    const int wid  = tid >> 5;
    const int lane = tid & 31;
    const int gid  = lane >> 2;      // 0..7
    const int tig  = lane & 3;       // 0..3
    const int warpM = wid >> 2;      // 0..1
    const int warpN = wid & 3;       // 0..3
    const int m0 = blockIdx.y * GM;
    const int n0 = blockIdx.x * GN;

    float acc[4][4][4];
    #pragma unroll
    for (int i = 0; i < 4; i++)
        #pragma unroll
        for (int j = 0; j < 4; j++)
            #pragma unroll
            for (int c = 0; c < 4; c++) acc[i][j][c] = 0.f;

    // ---- tile loader: 2048 x 16B chunks, 8 per thread ----
    // chunk c: 0..511 Ahi, 512..1023 Alo, 1024..1535 Bhi, 1536..2047 Blo
    uint32_t smem_base = smem_u32(smem);
    auto load_tile = [&](int s, int t) {
        const int k0 = t * GK;
        uint32_t stage = smem_base + (uint32_t)(s * STAGE_F * 4);
        #pragma unroll
        for (int j = 0; j < 8; j++) {
            int c = tid + j * 256;
            int pl = c >> 9;                 // 0..3
            int cc = c & 511;
            int row = cc >> 2;               // 0..127
            int c4  = cc & 3;                // 0..3
            const float* gsrc;
            size_t go;
            if (pl < 2) {
                go = (size_t)(m0 + row) * DIM + k0 + c4 * 4;
                gsrc = (pl == 0) ? (Ahi + go) : (Alo + go);
            } else {
                go = (size_t)(n0 + row) * DIM + k0 + c4 * 4;
                gsrc = (pl == 2) ? (Whi + go) : (Wlo + go);
            }
            uint32_t sa = stage + (uint32_t)((pl * PLANE_F + row * PITCH + c4 * 4) * 4);
            cp16(sa, gsrc);
        }
    };

    // prologue
    #pragma unroll
    for (int s = 0; s < STAGES; s++) {
        load_tile(s, s);
        CP_COMMIT();
    }

    const int aOffBase = warpM * 64 * PITCH;            // into A planes
    const int bOffBase = warpN * 32 * PITCH;            // into B planes

    for (int t = 0; t < NT_K; t++) {
        CP_WAIT(2);
        __syncthreads();
        const float* stg = smem + (t % STAGES) * STAGE_F;
        const float* sAh = stg;
        const float* sAl = stg + PLANE_F;
        const float* sBh = stg + 2 * PLANE_F;
        const float* sBl = stg + 3 * PLANE_F;

        #pragma unroll
        for (int kk = 0; kk < GK; kk += 8) {
            uint32_t Ah[4][4], Al[4][4], Bh[4][2], Bl[4][2];
            #pragma unroll
            for (int mi = 0; mi < 4; mi++) {
                int o = aOffBase + (mi * 16 + gid) * PITCH + kk + tig;
                Ah[mi][0] = __float_as_uint(sAh[o]);
                Ah[mi][1] = __float_as_uint(sAh[o + 8 * PITCH]);
                Ah[mi][2] = __float_as_uint(sAh[o + 4]);
                Ah[mi][3] = __float_as_uint(sAh[o + 8 * PITCH + 4]);
                Al[mi][0] = __float_as_uint(sAl[o]);
                Al[mi][1] = __float_as_uint(sAl[o + 8 * PITCH]);
                Al[mi][2] = __float_as_uint(sAl[o + 4]);
                Al[mi][3] = __float_as_uint(sAl[o + 8 * PITCH + 4]);
            }
            #pragma unroll
            for (int ni = 0; ni < 4; ni++) {
                int o = bOffBase + (ni * 8 + gid) * PITCH + kk + tig;
                Bh[ni][0] = __float_as_uint(sBh[o]);
                Bh[ni][1] = __float_as_uint(sBh[o + 4]);
                Bl[ni][0] = __float_as_uint(sBl[o]);
                Bl[ni][1] = __float_as_uint(sBl[o + 4]);
            }
            #pragma unroll
            for (int mi = 0; mi < 4; mi++)
                #pragma unroll
                for (int ni = 0; ni < 4; ni++) {
                    mma_tf32(acc[mi][ni], Ah[mi], Bh[ni]);
                    mma_tf32(acc[mi][ni], Ah[mi], Bl[ni]);
                    mma_tf32(acc[mi][ni], Al[mi], Bh[ni]);
                }
        }
        __syncthreads();
        if (t + STAGES < NT_K) load_tile(t % STAGES, t + STAGES);
        CP_COMMIT();
    }

    // ---- epilogue ----
    #pragma unroll
    for (int mi = 0; mi < 4; mi++) {
        #pragma unroll
        for (int half = 0; half < 2; half++) {
            size_t m = (size_t)(m0 + warpM * 64 + mi * 16 + gid + half * 8);
            #pragma unroll
            for (int ni = 0; ni < 4; ni++) {
                int n = n0 + warpN * 32 + ni * 8 + 2 * tig;
                float r0 = acc[mi][ni][half * 2 + 0];
                float r1 = acc[mi][ni][half * 2 + 1];
                float2 bs = *(const float2*)(bias + n);
                float2 bb = *(const float2*)(base + m * DIM + n);
                float2 o;
                o.x = bb.x + sign * (r0 + bs.x);
                o.y = bb.y + sign * (r1 + bs.y);
                *(float2*)(outp + m * DIM + n) = o;
                if (emit) {
                    float2 a2 = *(const float2*)(aN + n);
                    float2 c2 = *(const float2*)(cN + n);
                    float s0 = a2.x * o.x + c2.x;
                    float s1 = a2.y * o.y + c2.y;
                    float2 h2, l2;
                    h2.x = tf32r(s0); l2.x = tf32r(s0 - h2.x);
                    h2.y = tf32r(s1); l2.y = tf32r(s1 - h2.y);
                    *(float2*)(eHi + m * DIM + n) = h2;
                    *(float2*)(eLo + m * DIM + n) = l2;
                }
            }
        }
    }
}

// ---------------------------------------------------------------------------
extern "C" void kernel_launch(void* const* d_in, const int* in_sizes, int n_in,
                              void* d_out, int out_size)
{
    const float* x   = (const float*)d_in[0];
    const float* W1  = (const float*)d_in[2];
    const float* b1  = (const float*)d_in[3];
    const float* g1  = (const float*)d_in[4];
    const float* be1 = (const float*)d_in[5];
    const float* m1  = (const float*)d_in[6];
    const float* v1  = (const float*)d_in[7];
    const float* W3  = (const float*)d_in[8];
    const float* b3  = (const float*)d_in[9];
    const float* g3  = (const float*)d_in[10];
    const float* be3 = (const float*)d_in[11];
    const float* m3  = (const float*)d_in[12];
    const float* v3  = (const float*)d_in[13];
    const float* kop = (const float*)d_in[14];
    float* out = (float*)d_out;

    float *A, *B, *H0, *L0, *H1, *L1, *W1h, *W1l, *W3h, *W3l, *aF, *cF, *aG, *cG;
    cudaGetSymbolAddress((void**)&A,  g_A);
    cudaGetSymbolAddress((void**)&B,  g_B);
    cudaGetSymbolAddress((void**)&H0, g_H0);
    cudaGetSymbolAddress((void**)&L0, g_L0);
    cudaGetSymbolAddress((void**)&H1, g_H1);
    cudaGetSymbolAddress((void**)&L1, g_L1);
    cudaGetSymbolAddress((void**)&W1h, g_W1Thi);
    cudaGetSymbolAddress((void**)&W1l, g_W1Tlo);
    cudaGetSymbolAddress((void**)&W3h, g_W3Thi);
    cudaGetSymbolAddress((void**)&W3l, g_W3Tlo);
    cudaGetSymbolAddress((void**)&aF, g_aF);
    cudaGetSymbolAddress((void**)&cF, g_cF);
    cudaGetSymbolAddress((void**)&aG, g_aG);
    cudaGetSymbolAddress((void**)&cG, g_cG);

    static int smem_set = 0;
    if (!smem_set) {
        cudaFuncSetAttribute(gemm_tc_kernel, cudaFuncAttributeMaxDynamicSharedMemorySize,
                             SM_TOTAL);
        smem_set = 1;
    }

    dim3 ggrid(DIM / GN, NIMG / GM);           // (16, 24)
    const int SPLIT_BLKS = (int)(((size_t)NIMG * DIM + 255) / 256);
    const int MIX_BLKS   = (int)(((size_t)NIMG * IMGE + 255) / 256);
    const int SLICE_BLKS = (int)((T_SLICE + 255) / 256);
    dim3 wgrid(DIM / 32, DIM / 32), wblk(32, 8);

    bncoef_kernel<<<8, 256>>>(g1, be1, m1, v1, g3, be3, m3, v3);
    wprep_kernel<<<wgrid, wblk>>>(W1, W1h, W1l);
    wprep_kernel<<<wgrid, wblk>>>(W3, W3h, W3l);

    cudaMemcpyAsync(out + S0, x, T_FULL * sizeof(float), cudaMemcpyDeviceToDevice);
    slice_kernel<<<SLICE_BLKS, 256>>>(x, out + S5);

    // ---- Encoder ----
    split_prep_kernel<<<SPLIT_BLKS, 256>>>(x, A, B, aF, cF, H0, L0, 0);
    gemm_tc_kernel<<<ggrid, 256, SM_TOTAL>>>(H0, L0, W1h, W1l, b1, A, A, +1.0f,
                                             aG, cG, H1, L1, 1);
    gemm_tc_kernel<<<ggrid, 256, SM_TOTAL>>>(H1, L1, W3h, W3l, b3, B, B, +1.0f,
                                             aF, cF, H0, L0, 0);
    mix_kernel<<<MIX_BLKS, 256>>>(A, B, out + S1);
    slice_kernel<<<SLICE_BLKS, 256>>>(out + S1, out + S6);

    // ---- Decoder(phiX) ----
    split_prep_kernel<<<SPLIT_BLKS, 256>>>(out + S1, A, B, aG, cG, H0, L0, 1);
    gemm_tc_kernel<<<ggrid, 256, SM_TOTAL>>>(H0, L0, W3h, W3l, b3, B, B, -1.0f,
                                             aF, cF, H1, L1, 1);
    gemm_tc_kernel<<<ggrid, 256, SM_TOTAL>>>(H1, L1, W1h, W1l, b1, A, A, -1.0f,
                                             aF, cF, H0, L0, 0);
    mix_kernel<<<MIX_BLKS, 256>>>(A, B, out + S2);

    // ---- Koopman ----
    koop_kernel<<<NIMG, 256>>>(out + S1, kop, out + S3);

    // ---- Decoder(kPhix) ----
    split_prep_kernel<<<SPLIT_BLKS, 256>>>(out + S3, A, B, aG, cG, H0, L0, 1);
    gemm_tc_kernel<<<ggrid, 256, SM_TOTAL>>>(H0, L0, W3h, W3l, b3, B, B, -1.0f,
                                             aF, cF, H1, L1, 1);
    gemm_tc_kernel<<<ggrid, 256, SM_TOTAL>>>(H1, L1, W1h, W1l, b1, A, A, -1.0f,
                                             aF, cF, H0, L0, 0);
    mix_kernel<<<MIX_BLKS, 256>>>(A, B, out + S4);
}

// round 4
// speedup vs baseline: 2.6826x; 1.7702x over previous
#include <cuda_runtime.h>
#include <cuda_bf16.h>
#include <cstdint>

// ---------------------------------------------------------------------------
// Problem constants
// ---------------------------------------------------------------------------
#define CCN   256
#define STD   12
#define FS    64
#define HALF  32
#define NIMG  (CCN*STD)          // 3072
#define DIM   2048               // FS*HALF
#define IMGE  (FS*FS)            // 4096

static const size_t T_FULL  = (size_t)NIMG * IMGE;
static const size_t T_SLICE = (size_t)CCN * 11 * IMGE;

// Output section offsets (floats)
static const size_t S0 = 0;                    // x
static const size_t S1 = S0 + T_FULL;          // phiX
static const size_t S2 = S1 + T_FULL;          // dephiPhiX
static const size_t S3 = S2 + T_FULL;          // kPhix
static const size_t S4 = S3 + T_FULL;          // dePhiKPhiX
static const size_t S5 = S4 + T_FULL;          // x[:,1:]
static const size_t S6 = S5 + T_SLICE;         // phiX[:,1:]

// ---------------------------------------------------------------------------
// Scratch (device globals — no runtime allocation allowed)
// ---------------------------------------------------------------------------
__device__ float         g_A [(size_t)NIMG * DIM];
__device__ float         g_B [(size_t)NIMG * DIM];
__device__ __nv_bfloat16 g_H0[(size_t)NIMG * DIM];
__device__ __nv_bfloat16 g_L0[(size_t)NIMG * DIM];
__device__ __nv_bfloat16 g_H1[(size_t)NIMG * DIM];
__device__ __nv_bfloat16 g_L1[(size_t)NIMG * DIM];
__device__ __nv_bfloat16 g_W1Thi[(size_t)DIM * DIM];   // W1^T hi  [N,K]
__device__ __nv_bfloat16 g_W1Tlo[(size_t)DIM * DIM];
__device__ __nv_bfloat16 g_W3Thi[(size_t)DIM * DIM];
__device__ __nv_bfloat16 g_W3Tlo[(size_t)DIM * DIM];
__device__ float g_aF[DIM], g_cF[DIM], g_aG[DIM], g_cG[DIM];

// ---------------------------------------------------------------------------
// Helpers (base sm_103 target only — NO tcgen05 / arch-'a' features)
// ---------------------------------------------------------------------------
__device__ __forceinline__ uint32_t smem_u32(const void* p) {
    uint32_t a;
    asm("{ .reg .u64 t; cvta.to.shared.u64 t, %1; cvt.u32.u64 %0, t; }" : "=r"(a) : "l"(p));
    return a;
}

__device__ __forceinline__ void cp16(uint32_t saddr, const void* gptr) {
    asm volatile("cp.async.cg.shared.global [%0], [%1], 16;" :: "r"(saddr), "l"(gptr));
}
#define CP_COMMIT() asm volatile("cp.async.commit_group;" ::: "memory")
#define CP_WAIT(n)  asm volatile("cp.async.wait_group %0;" :: "n"(n) : "memory")

__device__ __forceinline__ void ldsm4(uint32_t* r, uint32_t addr) {
    asm volatile("ldmatrix.sync.aligned.m8n8.x4.shared.b16 {%0,%1,%2,%3}, [%4];"
                 : "=r"(r[0]), "=r"(r[1]), "=r"(r[2]), "=r"(r[3]) : "r"(addr));
}

__device__ __forceinline__ void mma_bf16(float* d, const uint32_t* a, const uint32_t* b) {
    asm volatile(
        "mma.sync.aligned.m16n8k16.row.col.f32.bf16.bf16.f32 "
        "{%0,%1,%2,%3}, {%4,%5,%6,%7}, {%8,%9}, {%0,%1,%2,%3};"
        : "+f"(d[0]), "+f"(d[1]), "+f"(d[2]), "+f"(d[3])
        : "r"(a[0]), "r"(a[1]), "r"(a[2]), "r"(a[3]), "r"(b[0]), "r"(b[1]));
}

__device__ __forceinline__ void bf16split(float s, __nv_bfloat16& h, __nv_bfloat16& l) {
    h = __float2bfloat16(s);
    l = __float2bfloat16(s - __bfloat162float(h));
}

// ---------------------------------------------------------------------------
// BN coefficient precompute
// ---------------------------------------------------------------------------
__global__ void bncoef_kernel(const float* __restrict__ g1, const float* __restrict__ be1,
                              const float* __restrict__ m1, const float* __restrict__ v1,
                              const float* __restrict__ g3, const float* __restrict__ be3,
                              const float* __restrict__ m3, const float* __restrict__ v3)
{
    int k = blockIdx.x * blockDim.x + threadIdx.x;
    if (k < DIM) {
        float aF = g1[k] * rsqrtf(v1[k] + 1e-3f);
        g_aF[k] = aF;  g_cF[k] = be1[k] - aF * m1[k];
        float aG = g3[k] * rsqrtf(v3[k] + 1e-3f);
        g_aG[k] = aG;  g_cG[k] = be3[k] - aG * m3[k];
    }
}

// ---------------------------------------------------------------------------
// Weight prep: W [K,N] -> W^T [N,K] split into bf16 hi/lo planes
// ---------------------------------------------------------------------------
__global__ void wprep_kernel(const float* __restrict__ W, __nv_bfloat16* __restrict__ Thi,
                             __nv_bfloat16* __restrict__ Tlo)
{
    __shared__ float t[32][33];
    int bn = blockIdx.x * 32;
    int bk = blockIdx.y * 32;
    int tx = threadIdx.x, ty = threadIdx.y;   // 32 x 8
    #pragma unroll
    for (int i = 0; i < 32; i += 8)
        t[ty + i][tx] = W[(size_t)(bk + ty + i) * DIM + bn + tx];
    __syncthreads();
    #pragma unroll
    for (int i = 0; i < 32; i += 8) {
        float v = t[tx][ty + i];
        size_t o = (size_t)(bn + ty + i) * DIM + bk + tx;
        __nv_bfloat16 h, l;
        bf16split(v, h, l);
        Thi[o] = h;
        Tlo[o] = l;
    }
}

// ---------------------------------------------------------------------------
// Checkerboard split + BN + bf16 hi/lo prep of one half
// ---------------------------------------------------------------------------
__global__ void split_prep_kernel(const float* __restrict__ x, float* __restrict__ u1,
                                  float* __restrict__ u2,
                                  const float* __restrict__ aC, const float* __restrict__ cC,
                                  __nv_bfloat16* __restrict__ hi,
                                  __nv_bfloat16* __restrict__ lo,
                                  int prep_first)
{
    size_t idx = (size_t)blockIdx.x * blockDim.x + threadIdx.x;
    if (idx >= (size_t)NIMG * DIM) return;
    int n = (int)(idx >> 11);
    int i = (int)((idx >> 5) & 63);
    int j = (int)(idx & 31);
    int p = i & 1;
    const float* row = x + ((size_t)n << 12) + ((size_t)i << 6) + ((size_t)j << 1);
    float v1 = row[p];
    float v2 = row[1 - p];
    u1[idx] = v1;
    u2[idx] = v2;
    int k = (int)(idx & 2047);
    float s = aC[k] * (prep_first ? v1 : v2) + cC[k];
    __nv_bfloat16 h, l;
    bf16split(s, h, l);
    hi[idx] = h;
    lo[idx] = l;
}

// ---------------------------------------------------------------------------
// Mix (+ optional fused [:,1:] slice of the mixed tensor)
// ---------------------------------------------------------------------------
__global__ void mix_kernel(const float* __restrict__ v1b, const float* __restrict__ w2b,
                           float* __restrict__ y, float* __restrict__ ysl)
{
    size_t idx = (size_t)blockIdx.x * blockDim.x + threadIdx.x;
    if (idx >= (size_t)NIMG * IMGE) return;
    int n = (int)(idx >> 12);
    int r = (int)((idx >> 6) & 63);
    int c = (int)(idx & 63);
    const float* v1 = v1b + ((size_t)n << 11) + ((size_t)r << 5);
    const float* w2 = w2b + ((size_t)n << 11) + ((size_t)r << 5);
    float val;
    if ((r & 1) == 0) {
        val = (c & 1) ? w2[(c - 1) >> 1] : v1[c >> 1];
    } else {
        val = (c & 1) ? v1[((c + 1) >> 1) & 31] : w2[((c >> 1) + 31) & 31];
    }
    y[idx] = val;
    if (ysl) {
        int s = n % STD;
        if (s >= 1) {
            int cc = n / STD;
            size_t e = idx & 4095;
            ysl[((size_t)(cc * 11 + s - 1) << 12) + e] = val;
        }
    }
}

// ---------------------------------------------------------------------------
// Copy x to out section 0 and write x[:,1:] slice in the same pass
// ---------------------------------------------------------------------------
__global__ void copyslice_kernel(const float* __restrict__ x, float* __restrict__ dst,
                                 float* __restrict__ dsl)
{
    size_t idx = (size_t)blockIdx.x * blockDim.x + threadIdx.x;
    if (idx >= T_FULL) return;
    float v = x[idx];
    dst[idx] = v;
    int n = (int)(idx >> 12);
    int s = n % STD;
    if (s >= 1) {
        int cc = n / STD;
        size_t e = idx & 4095;
        dsl[((size_t)(cc * 11 + s - 1) << 12) + e] = v;
    }
}

// ---------------------------------------------------------------------------
// Koopman step
// ---------------------------------------------------------------------------
__global__ void koop_kernel(const float* __restrict__ phi, const float* __restrict__ kop,
                            float* __restrict__ outk)
{
    __shared__ float sk[64][64];
    __shared__ float si[64][64];
    int m = blockIdx.x;
    int nprime = m / STD, s = m % STD;
    int q = nprime >> 2, b = nprime & 3;
    int nin = b * 64 + q;
    const float* src = phi + (size_t)(nin * STD + s) * IMGE;
    float* dst = outk + (size_t)m * IMGE;
    int t = threadIdx.x;
    for (int e = t; e < IMGE; e += 256) {
        sk[e >> 6][e & 63] = kop[e];
        si[e >> 6][e & 63] = src[e];
    }
    __syncthreads();
    for (int e = t; e < IMGE; e += 256) {
        int i = e >> 6, c = e & 63;
        float acc = 0.f;
        #pragma unroll
        for (int j = 0; j < 64; j++) acc += si[i][j] * sk[j][c];
        dst[e] = acc;
    }
}

// ---------------------------------------------------------------------------
// BF16x3 mma.sync GEMM (m16n8k16 + ldmatrix).
//   out[m,n] = base[m,n] + sign*( sum_k A[m,k]*WT[n,k] + bias[n] )
// A planes [M,K] bf16 hi/lo; WT planes [N,K] bf16 hi/lo.
// CTA tile 128x128, BK=32, 8 warps (2x4), warp tile 64x32, 3-stage cp.async.
// SMEM rows pitch 80B (64B data + 16B pad) -> conflict-free ldmatrix.
// ---------------------------------------------------------------------------
#define GM 128
#define GN 128
#define BK 32
#define NT_K (DIM / BK)            // 64
#define PITCHB 80                  // bytes per smem row
#define PLANE_B (128 * PITCHB)     // 10240
#define STAGE_B (4 * PLANE_B)      // 40960
#define STAGES 3
#define SM_TOTAL (STAGES * STAGE_B)

__global__ void __launch_bounds__(256, 1)
gemm_tc_kernel(const __nv_bfloat16* __restrict__ Ahi, const __nv_bfloat16* __restrict__ Alo,
               const __nv_bfloat16* __restrict__ Whi, const __nv_bfloat16* __restrict__ Wlo,
               const float* __restrict__ bias, const float* base, float* outp, float sign,
               const float* __restrict__ aN, const float* __restrict__ cN,
               __nv_bfloat16* eHi, __nv_bfloat16* eLo, int emit)
{
    extern __shared__ char smem[];
    uint32_t sb = smem_u32(smem);
    const int tid  = threadIdx.x;
    const int wid  = tid >> 5;
    const int lane = tid & 31;
    const int gid  = lane >> 2;      // 0..7
    const int tig  = lane & 3;       // 0..3
    const int warpM = wid >> 2;      // 0..1
    const int warpN = wid & 3;       // 0..3
    const int m0 = blockIdx.y * GM;
    const int n0 = blockIdx.x * GN;

    float acc[4][4][4];
    #pragma unroll
    for (int i = 0; i < 4; i++)
        #pragma unroll
        for (int j = 0; j < 4; j++)
            #pragma unroll
            for (int c = 0; c < 4; c++) acc[i][j][c] = 0.f;

    // ldmatrix per-lane address components
    const int t8 = lane >> 3;       // tile index 0..3
    const int r8 = lane & 7;        // row within tile
    // A tiles: row offset (t8&1)*8, k offset (t8>>1)*8
    const uint32_t aoff = (uint32_t)((warpM * 64 + (t8 & 1) * 8 + r8) * PITCHB + (t8 >> 1) * 16);
    // B tiles: n offset (t8>>1)*8, k offset (t8&1)*8
    const uint32_t boff = (uint32_t)(2 * PLANE_B +
                          (warpN * 32 + (t8 >> 1) * 8 + r8) * PITCHB + (t8 & 1) * 16);

    // ---- tile loader: 2048 x 16B chunks (8 bf16 each), 8 per thread ----
    auto load_tile = [&](int s, int t) {
        const int k0 = t * BK;
        uint32_t stage = sb + (uint32_t)(s * STAGE_B);
        #pragma unroll
        for (int j = 0; j < 8; j++) {
            int c = tid + j * 256;
            int pl = c >> 9;                 // plane 0..3
            int cc = c & 511;
            int row = cc >> 2;               // 0..127
            int c4  = cc & 3;                // 16B chunk in row
            const __nv_bfloat16* g;
            if (pl == 0)      g = Ahi + (size_t)(m0 + row) * DIM + k0 + c4 * 8;
            else if (pl == 1) g = Alo + (size_t)(m0 + row) * DIM + k0 + c4 * 8;
            else if (pl == 2) g = Whi + (size_t)(n0 + row) * DIM + k0 + c4 * 8;
            else              g = Wlo + (size_t)(n0 + row) * DIM + k0 + c4 * 8;
            cp16(stage + (uint32_t)(pl * PLANE_B + row * PITCHB + c4 * 16), g);
        }
    };

    #pragma unroll
    for (int s = 0; s < STAGES; s++) {
        load_tile(s, s);
        CP_COMMIT();
    }

    for (int t = 0; t < NT_K; t++) {
        CP_WAIT(2);
        __syncthreads();
        uint32_t stg = sb + (uint32_t)((t % STAGES) * STAGE_B);
        uint32_t aB = stg + aoff;
        uint32_t bB = stg + boff;

        #pragma unroll
        for (int kk = 0; kk < BK; kk += 16) {
            uint32_t Ah[4][4], Al[4][4], Bh[4][2], Bl[4][2];
            #pragma unroll
            for (int mi = 0; mi < 4; mi++) {
                uint32_t a = aB + (uint32_t)(mi * 16 * PITCHB + kk * 2);
                ldsm4(Ah[mi], a);
                ldsm4(Al[mi], a + PLANE_B);
            }
            #pragma unroll
            for (int nip = 0; nip < 2; nip++) {
                uint32_t b = bB + (uint32_t)(nip * 16 * PITCHB + kk * 2);
                uint32_t th[4], tl[4];
                ldsm4(th, b);
                ldsm4(tl, b + PLANE_B);
                Bh[nip * 2][0] = th[0]; Bh[nip * 2][1] = th[1];
                Bh[nip * 2 + 1][0] = th[2]; Bh[nip * 2 + 1][1] = th[3];
                Bl[nip * 2][0] = tl[0]; Bl[nip * 2][1] = tl[1];
                Bl[nip * 2 + 1][0] = tl[2]; Bl[nip * 2 + 1][1] = tl[3];
            }
            #pragma unroll
            for (int mi = 0; mi < 4; mi++)
                #pragma unroll
                for (int ni = 0; ni < 4; ni++) {
                    mma_bf16(acc[mi][ni], Ah[mi], Bh[ni]);
                    mma_bf16(acc[mi][ni], Ah[mi], Bl[ni]);
                    mma_bf16(acc[mi][ni], Al[mi], Bh[ni]);
                }
        }
        __syncthreads();
        if (t + STAGES < NT_K) load_tile(t % STAGES, t + STAGES);
        CP_COMMIT();
    }

    // ---- epilogue ----
    #pragma unroll
    for (int mi = 0; mi < 4; mi++) {
        #pragma unroll
        for (int half = 0; half < 2; half++) {
            size_t m = (size_t)(m0 + warpM * 64 + mi * 16 + gid + half * 8);
            #pragma unroll
            for (int ni = 0; ni < 4; ni++) {
                int n = n0 + warpN * 32 + ni * 8 + 2 * tig;
                float r0 = acc[mi][ni][half * 2 + 0];
                float r1 = acc[mi][ni][half * 2 + 1];
                float2 bs = *(const float2*)(bias + n);
                float2 bb = *(const float2*)(base + m * DIM + n);
                float2 o;
                o.x = bb.x + sign * (r0 + bs.x);
                o.y = bb.y + sign * (r1 + bs.y);
                *(float2*)(outp + m * DIM + n) = o;
                if (emit) {
                    float2 a2 = *(const float2*)(aN + n);
                    float2 c2 = *(const float2*)(cN + n);
                    float s0 = a2.x * o.x + c2.x;
                    float s1 = a2.y * o.y + c2.y;
                    __nv_bfloat162 h2, l2;
                    bf16split(s0, h2.x, l2.x);
                    bf16split(s1, h2.y, l2.y);
                    *(__nv_bfloat162*)(eHi + m * DIM + n) = h2;
                    *(__nv_bfloat162*)(eLo + m * DIM + n) = l2;
                }
            }
        }
    }
}

// ---------------------------------------------------------------------------
extern "C" void kernel_launch(void* const* d_in, const int* in_sizes, int n_in,
                              void* d_out, int out_size)
{
    const float* x   = (const float*)d_in[0];
    const float* W1  = (const float*)d_in[2];
    const float* b1  = (const float*)d_in[3];
    const float* g1  = (const float*)d_in[4];
    const float* be1 = (const float*)d_in[5];
    const float* m1  = (const float*)d_in[6];
    const float* v1  = (const float*)d_in[7];
    const float* W3  = (const float*)d_in[8];
    const float* b3  = (const float*)d_in[9];
    const float* g3  = (const float*)d_in[10];
    const float* be3 = (const float*)d_in[11];
    const float* m3  = (const float*)d_in[12];
    const float* v3  = (const float*)d_in[13];
    const float* kop = (const float*)d_in[14];
    float* out = (float*)d_out;

    float *A, *B, *aF, *cF, *aG, *cG;
    __nv_bfloat16 *H0, *L0, *H1, *L1, *W1h, *W1l, *W3h, *W3l;
    cudaGetSymbolAddress((void**)&A,  g_A);
    cudaGetSymbolAddress((void**)&B,  g_B);
    cudaGetSymbolAddress((void**)&H0, g_H0);
    cudaGetSymbolAddress((void**)&L0, g_L0);
    cudaGetSymbolAddress((void**)&H1, g_H1);
    cudaGetSymbolAddress((void**)&L1, g_L1);
    cudaGetSymbolAddress((void**)&W1h, g_W1Thi);
    cudaGetSymbolAddress((void**)&W1l, g_W1Tlo);
    cudaGetSymbolAddress((void**)&W3h, g_W3Thi);
    cudaGetSymbolAddress((void**)&W3l, g_W3Tlo);
    cudaGetSymbolAddress((void**)&aF, g_aF);
    cudaGetSymbolAddress((void**)&cF, g_cF);
    cudaGetSymbolAddress((void**)&aG, g_aG);
    cudaGetSymbolAddress((void**)&cG, g_cG);

    static int smem_set = 0;
    if (!smem_set) {
        cudaFuncSetAttribute(gemm_tc_kernel, cudaFuncAttributeMaxDynamicSharedMemorySize,
                             SM_TOTAL);
        smem_set = 1;
    }

    dim3 ggrid(DIM / GN, NIMG / GM);           // (16, 24)
    const int SPLIT_BLKS = (int)(((size_t)NIMG * DIM + 255) / 256);
    const int MIX_BLKS   = (int)(((size_t)NIMG * IMGE + 255) / 256);
    const int FULL_BLKS  = (int)((T_FULL + 255) / 256);
    dim3 wgrid(DIM / 32, DIM / 32), wblk(32, 8);

    bncoef_kernel<<<8, 256>>>(g1, be1, m1, v1, g3, be3, m3, v3);
    wprep_kernel<<<wgrid, wblk>>>(W1, W1h, W1l);
    wprep_kernel<<<wgrid, wblk>>>(W3, W3h, W3l);

    // x -> sections 0 and 5 in one pass
    copyslice_kernel<<<FULL_BLKS, 256>>>(x, out + S0, out + S5);

    // ---- Encoder ----
    split_prep_kernel<<<SPLIT_BLKS, 256>>>(x, A, B, aF, cF, H0, L0, 0);
    gemm_tc_kernel<<<ggrid, 256, SM_TOTAL>>>(H0, L0, W1h, W1l, b1, A, A, +1.0f,
                                             aG, cG, H1, L1, 1);
    gemm_tc_kernel<<<ggrid, 256, SM_TOTAL>>>(H1, L1, W3h, W3l, b3, B, B, +1.0f,
                                             aF, cF, H0, L0, 0);
    mix_kernel<<<MIX_BLKS, 256>>>(A, B, out + S1, out + S6);   // phiX + phiX[:,1:]

    // ---- Decoder(phiX) ----
    split_prep_kernel<<<SPLIT_BLKS, 256>>>(out + S1, A, B, aG, cG, H0, L0, 1);
    gemm_tc_kernel<<<ggrid, 256, SM_TOTAL>>>(H0, L0, W3h, W3l, b3, B, B, -1.0f,
                                             aF, cF, H1, L1, 1);
    gemm_tc_kernel<<<ggrid, 256, SM_TOTAL>>>(H1, L1, W1h, W1l, b1, A, A, -1.0f,
                                             aF, cF, H0, L0, 0);
    mix_kernel<<<MIX_BLKS, 256>>>(A, B, out + S2, nullptr);    // dephiPhiX

    // ---- Koopman ----
    koop_kernel<<<NIMG, 256>>>(out + S1, kop, out + S3);       // kPhix

    // ---- Decoder(kPhix) ----
    split_prep_kernel<<<SPLIT_BLKS, 256>>>(out + S3, A, B, aG, cG, H0, L0, 1);
    gemm_tc_kernel<<<ggrid, 256, SM_TOTAL>>>(H0, L0, W3h, W3l, b3, B, B, -1.0f,
                                             aF, cF, H1, L1, 1);
    gemm_tc_kernel<<<ggrid, 256, SM_TOTAL>>>(H1, L1, W1h, W1l, b1, A, A, -1.0f,
                                             aF, cF, H0, L0, 0);
    mix_kernel<<<MIX_BLKS, 256>>>(A, B, out + S4, nullptr);    // dePhiKPhiX
}